// round 17
// baseline (speedup 1.0000x reference)
#include <cuda_runtime.h>

typedef unsigned long long ull;

#define BATCH 36
#define TWIN 60
#define DECAY 0.3f
#define THRESH 0.5f
#define NBLOCKS 444

// packed f32x2 fma: d = a*b + d per 32-bit lane (bit-exact IEEE fma per lane)
#define FMA2(d, a, b) asm("fma.rn.f32x2 %0, %1, %2, %0;" : "+l"(d) : "l"(a), "l"(b))

#define CP_ASYNC4(dst, src)  asm volatile("cp.async.ca.shared.global [%0], [%1], 4;"  :: "r"(dst), "l"(src))
#define CP_ASYNC16(dst, src) asm volatile("cp.async.cg.shared.global [%0], [%1], 16;" :: "r"(dst), "l"(src))
#define CP_COMMIT()          asm volatile("cp.async.commit_group;" ::: "memory")
#define CP_WAIT0()           asm volatile("cp.async.wait_group 0;" ::: "memory")

union F2 { ull u; float2 f; };

__device__ __forceinline__ ull dup2(float v) {
    F2 d; d.f.x = v; d.f.y = v; return d.u;
}

__device__ __forceinline__ unsigned smem_u32(const void* p) {
    return (unsigned)__cvta_generic_to_shared(p);
}

// ---------------- persistent LIAF state: pre = (m>THRESH) ? 0 : m*DECAY ----------
__device__ __align__(16) float g_c0_pre[BATCH*64*32*32];
__device__ __align__(16) float g_c1_pre[BATCH*128*32*32];
__device__ __align__(16) float g_p1_pre[BATCH*128*16*16];
__device__ __align__(16) float g_c2_pre[BATCH*128*16*16];
__device__ __align__(16) float g_p2_pre[BATCH*128*8*8];
__device__ __align__(16) float g_h1_pre[BATCH*256];
__device__ __align__(16) float g_h2_pre[BATCH*11];
__device__ __align__(16) float g_acc[BATCH*11];

// ---------------- parity double-buffered activations ----------------
__device__ __align__(16) float g_act0 [2][BATCH*64*32*32];
__device__ __align__(16) float g_actp1[2][BATCH*128*16*16];
__device__ __align__(16) float g_actp2[2][BATCH*128*8*8];
__device__ __align__(16) float g_acth1[2][BATCH*256];

// ---------------- pre-binarized input, t-major: [t][b*2+ic][y][x] ----------------
__device__ __align__(16) float g_bin[TWIN*BATCH*2*32*32];

// ---------------- transposed weights: Wt[c][oc], c = ic*9 + k ----------------
__device__ __align__(16) float g_Wt1[576*128];   // conv1: 64*9 x 128
__device__ __align__(16) float g_Wt2[1152*128];  // conv2: 128*9 x 128

// ---------------- global barrier state ----------------
__device__ unsigned g_bar_count;
__device__ unsigned g_bar_epoch;

__device__ __forceinline__ float liaf_pre(float u, float* prep) {
    float m = *prep + u;
    *prep = (m > THRESH) ? 0.0f : m * DECAY;
    return fmaxf(m, 0.0f);
}

// ---------------- zero state (+ barrier reset) ----------------
__global__ void zero_state_kernel() {
    int i = blockIdx.x * blockDim.x + threadIdx.x;
    if (i == 0) { g_bar_count = 0u; g_bar_epoch = 0u; }
    if (i < BATCH*64*32*32)  g_c0_pre[i] = 0.f;
    if (i < BATCH*128*32*32) g_c1_pre[i] = 0.f;
    if (i < BATCH*128*16*16) { g_p1_pre[i] = 0.f; g_c2_pre[i] = 0.f; }
    if (i < BATCH*128*8*8)   g_p2_pre[i] = 0.f;
    if (i < BATCH*256)       g_h1_pre[i] = 0.f;
    if (i < BATCH*11)        { g_h2_pre[i] = 0.f; g_acc[i] = 0.f; }
}

// ---------------- weight transpose (once per launch) ----------------
__global__ void prep_weights_kernel(const float* __restrict__ W1,
                                    const float* __restrict__ W2) {
    int i = blockIdx.x * blockDim.x + threadIdx.x;
    if (i < 576*128)  g_Wt1[i] = W1[(i & 127)*576  + (i >> 7)];
    if (i < 1152*128) g_Wt2[i] = W2[(i & 127)*1152 + (i >> 7)];
}

// ---------------- input binarize + transpose (once per launch) ----------------
__global__ void prep_bin_kernel(const float* __restrict__ data) {
    int i = blockIdx.x * blockDim.x + threadIdx.x;
    if (i >= TWIN*BATCH*2*32*32) return;
    int t = i / 73728, sp = i - t * 73728;
    g_bin[i] = (data[(size_t)sp * TWIN + t] > 1.0f) ? 1.0f : 0.0f;
}

// ---------------- device grid barrier (all NBLOCKS blocks) ----------------
__device__ __forceinline__ void grid_barrier(unsigned& epoch) {
    __syncthreads();
    if (threadIdx.x == 0) {
        __threadfence();                       // publish this block's writes
        unsigned arrived = atomicAdd(&g_bar_count, 1u);
        if (arrived == NBLOCKS - 1u) {
            g_bar_count = 0u;
            __threadfence();
            atomicAdd(&g_bar_epoch, 1u);       // release
        } else {
            unsigned target = epoch + 1u, e;
            do {
                asm volatile("ld.acquire.gpu.u32 %0, [%1];"
                             : "=r"(e) : "l"(&g_bar_epoch) : "memory");
                if (e < target) __nanosleep(64);
            } while (e < target);
        }
    }
    __syncthreads();
    epoch += 1u;
    __threadfence();   // gpu-scope fence: drop stale L1 lines before next phase
}

// ---------------- conv0 unit: prebinarized 2->64 conv + LIAF ----------------
__device__ __forceinline__ void conv0_unit(
    float* __restrict__ smem,
    const float* __restrict__ W0, const float* __restrict__ b0,
    float* __restrict__ act0_out, int t, int tile, int b)
{
    float* xs = smem;            // [2][10][12] = 240
    float* ws = smem + 240;      // [64][19]    = 1216
    int ty0 = (tile >> 2) * 8, tx0 = (tile & 3) * 8;
    int tid = threadIdx.x;
    const float* bt = g_bin + (size_t)t * 73728;

    __syncthreads();
    for (int i = tid; i < 200; i += 256) {
        int ic = i / 100, r = (i / 10) % 10, c = i % 10;
        int gy = ty0 + r - 1, gx = tx0 + c - 1;
        float v = 0.f;
        if ((unsigned)gy < 32u && (unsigned)gx < 32u)
            v = bt[((b*2 + ic)*32 + gy)*32 + gx];
        xs[(ic*10 + r)*12 + c] = v;
    }
    for (int i = tid; i < 1152; i += 256) {
        int oc = i / 18, r = i % 18;
        ws[oc*19 + r] = W0[i];
    }
    __syncthreads();

    int p  = tid & 63;
    int cg = tid >> 6;
    int py = p >> 3, px = p & 7;
    int oc0 = cg * 16;

    float acc[16];
#pragma unroll
    for (int o = 0; o < 16; o++) acc[o] = 0.f;

#pragma unroll
    for (int ic = 0; ic < 2; ic++) {
        float xr[9];
#pragma unroll
        for (int r = 0; r < 3; r++)
#pragma unroll
            for (int c = 0; c < 3; c++)
                xr[r*3 + c] = xs[(ic*10 + py + r)*12 + px + c];
#pragma unroll
        for (int k = 0; k < 9; k++) {
            float x = xr[k];
#pragma unroll
            for (int o = 0; o < 16; o++)
                acc[o] = fmaf(x, ws[(oc0 + o)*19 + ic*9 + k], acc[o]);
        }
    }

    int gy = ty0 + py, gx = tx0 + px;
#pragma unroll
    for (int o = 0; o < 16; o++) {
        int oc = oc0 + o;
        int idx = ((b*64 + oc)*32 + gy)*32 + gx;
        act0_out[idx] = liaf_pre(acc[o] + b0[oc], &g_c0_pre[idx]);
    }
}

// ---------------- f32x2 conv (3x3) + LIAF + 2x2 pool + LIAF -------------------
// v6: cp.async chunk staging (4 ch/chunk) + direct per-ky row loads (R4 inner;
// no rolling cache -> ~80 regs, enables 3 blocks/SM). Accumulation order per
// output unchanged: (chunk asc, il asc, ky, kx).
template<int HW, int TILE_R, int PXC, int CIN>
__device__ __forceinline__ void conv_pool_unit(
    float* __restrict__ smem,
    const float* __restrict__ in, const float* __restrict__ Wt,
    const float* __restrict__ bias, float* __restrict__ conv_pre,
    float* __restrict__ pool_pre, float* __restrict__ pool_out,
    int ocbase, int t0r, int t0c, int b)
{
    constexpr int XROWS = TILE_R + 2;
    constexpr int XSTR  = 13;
    constexpr int PCOLS = 8 / PXC;
    constexpr int RW    = PXC + 2;
    constexpr int XCH   = 4 * XROWS * XSTR;
    constexpr int WCH   = 36 * 64;
    constexpr int BUF   = XCH + WCH;
    constexpr int NCHUNK = CIN / 4;

    const int tid  = threadIdx.x;
    const int pos  = tid & 15;
    const int g    = tid >> 4;
    const int prow = pos / PCOLS;
    const int pcol = pos % PCOLS;
    const int qy   = prow * 2;
    const int qx   = pcol * PXC;

    __syncthreads();
    for (int i = tid; i < XCH; i += 256) { smem[i] = 0.f; smem[BUF + i] = 0.f; }
    __syncthreads();

    auto stage = [&](int c, float* dst) {
        int ch = c >> 1, hf = c & 1;
        unsigned dx = smem_u32(dst);
        for (int i = tid; i < 4 * XROWS * 10; i += 256) {
            int il = i / (XROWS * 10);
            int rem = i - il * (XROWS * 10);
            int r = rem / 10, cc = rem - r * 10;
            int gy = t0r + r - 1, gx = t0c + cc - 1;
            if ((unsigned)gy < (unsigned)HW && (unsigned)gx < (unsigned)HW) {
                const float* src =
                    &in[((b*CIN + ch*8 + hf*4 + il)*HW + gy)*HW + gx];
                CP_ASYNC4(dx + ((il*XROWS + r)*XSTR + cc)*4, src);
            }
        }
        unsigned dw = dx + XCH*4;
        for (int i = tid; i < 36 * 16; i += 256) {
            int j = i >> 4, q = i & 15;
            const float* src = &Wt[(ch*72 + hf*36 + j)*128 + ocbase + q*4];
            CP_ASYNC16(dw + (j*64 + q*4)*4, src);
        }
        CP_COMMIT();
    };

    ull acc[2][PXC][2];
#pragma unroll
    for (int py = 0; py < 2; py++)
#pragma unroll
        for (int px = 0; px < PXC; px++) {
            acc[py][px][0] = 0ull; acc[py][px][1] = 0ull;
        }

    stage(0, smem);

    for (int c = 0; c < NCHUNK; c++) {
        CP_WAIT0();
        __syncthreads();
        if (c + 1 < NCHUNK) stage(c + 1, ((c + 1) & 1) ? smem + BUF : smem);
        const float* cur = (c & 1) ? smem + BUF : smem;
        const float* xsb = cur;
        const float* wsb = cur + XCH;

#pragma unroll 1
        for (int il = 0; il < 4; il++) {
            const float* xb = &xsb[il * (XROWS * XSTR) + qx];
            const float* wb = &wsb[il * (9*64) + g*4];

#pragma unroll
            for (int ky = 0; ky < 3; ky++) {
                ull xd0[RW], xd1[RW];
#pragma unroll
                for (int cc = 0; cc < RW; cc++)
                    xd0[cc] = dup2(xb[(qy + ky + 0) * XSTR + cc]);
#pragma unroll
                for (int cc = 0; cc < RW; cc++)
                    xd1[cc] = dup2(xb[(qy + ky + 1) * XSTR + cc]);
#pragma unroll
                for (int kx = 0; kx < 3; kx++) {
                    ull w0 = *(const ull*)&wb[(ky*3 + kx)*64];
                    ull w1 = *(const ull*)&wb[(ky*3 + kx)*64 + 2];
#pragma unroll
                    for (int px = 0; px < PXC; px++) {
                        FMA2(acc[0][px][0], xd0[px + kx], w0);
                        FMA2(acc[0][px][1], xd0[px + kx], w1);
                        FMA2(acc[1][px][0], xd1[px + kx], w0);
                        FMA2(acc[1][px][1], xd1[px + kx], w1);
                    }
                }
            }
        }
        __syncthreads();
    }

    const int gy0 = t0r + qy, gx0 = t0c + qx;
#pragma unroll
    for (int og = 0; og < 2; og++) {
#pragma unroll
        for (int half = 0; half < 2; half++) {
            int oc = ocbase + g*4 + og*2 + half;
            float bv = bias[oc];
            float a[2][PXC];
#pragma unroll
            for (int py = 0; py < 2; py++)
#pragma unroll
                for (int px = 0; px < PXC; px++) {
                    F2 v; v.u = acc[py][px][og];
                    float u = (half ? v.f.y : v.f.x) + bv;
                    int idx = ((b*128 + oc)*HW + gy0 + py)*HW + gx0 + px;
                    a[py][px] = liaf_pre(u, &conv_pre[idx]);
                }
#pragma unroll
            for (int w = 0; w < PXC/2; w++) {
                float u = 0.25f * (((a[0][w*2] + a[0][w*2+1]) + a[1][w*2]) + a[1][w*2+1]);
                int pidx = ((b*128 + oc)*(HW/2) + (gy0 >> 1))*(HW/2) + (gx0 >> 1) + w;
                pool_out[pidx] = liaf_pre(u, &pool_pre[pidx]);
            }
        }
    }
}

// ---------------- fc2 block-unit (8 warps cover 8 of 396 (b,row) pairs) --------
__device__ __forceinline__ void fc2_unit(
    const float* __restrict__ Wf2, const float* __restrict__ bf2,
    const float* __restrict__ acth1_in, int unit)
{
    int warp = threadIdx.x >> 5, lane = threadIdx.x & 31;
    int gw = unit * 8 + warp;
    if (gw >= 396) return;
    int b = gw / 11, row = gw % 11;
    float s = 0.f;
#pragma unroll
    for (int k = lane; k < 256; k += 32)
        s += acth1_in[b*256 + k] * Wf2[row*256 + k];
#pragma unroll
    for (int off = 16; off; off >>= 1)
        s += __shfl_down_sync(0xffffffffu, s, off);
    if (lane == 0) {
        int idx = b*11 + row;
        float o = liaf_pre(s + bf2[row], &g_h2_pre[idx]);
        g_acc[idx] += o;
    }
}

// ---------------- fc1 block-unit (8 warps; gw = unit*8+warp) ----------------
__device__ __forceinline__ void fc1_unit(
    const float* __restrict__ Wf1, const float* __restrict__ bf1,
    const float* __restrict__ actp2_in, float* __restrict__ acth1_out, int unit)
{
    int warp = threadIdx.x >> 5, lane = threadIdx.x & 31;
    int gw = unit * 8 + warp;
    if (gw >= 1536) return;
    int o = gw / 6, bg = gw % 6;
    const float4* wp = (const float4*)(Wf1 + (size_t)o * 8192);
    float bv = bf1[o];
    int b0i = bg * 6;
    for (int b = b0i; b < b0i + 6; b++) {
        const float4* xp = (const float4*)(actp2_in + (size_t)b * 8192);
        float s = 0.f;
#pragma unroll 8
        for (int i = lane; i < 2048; i += 32) {
            float4 x = xp[i], w = wp[i];
            s += x.x*w.x; s += x.y*w.y; s += x.z*w.z; s += x.w*w.w;
        }
#pragma unroll
        for (int off = 16; off; off >>= 1)
            s += __shfl_down_sync(0xffffffffu, s, off);
        if (lane == 0) {
            int idx = b*256 + o;
            acth1_out[idx] = liaf_pre(s + bv, &g_h1_pre[idx]);
        }
    }
}

// ---------------- mega kernel: 5-stage pipeline, one barrier per phase ---------
// 864 uniform heavy units: 0..575 = conv1 (16x8-tile oc-halves),
// 576..863 = conv2. Strided over 444 blocks (3 blocks/SM) -> <=2 per block.
__global__ __launch_bounds__(256, 3) void mega_kernel(
    const float* __restrict__ W0, const float* __restrict__ b0,
    const float* __restrict__ b1, const float* __restrict__ b2,
    const float* __restrict__ Wf1, const float* __restrict__ bf1,
    const float* __restrict__ Wf2, const float* __restrict__ bf2,
    float* __restrict__ out)
{
    __shared__ __align__(16) float smem[6480];
    unsigned epoch = 0u;
    const int blk = blockIdx.x;
    const int tid = threadIdx.x;

    for (int p = 0; p < TWIN + 4; p++) {
        int t1 = p - 1;   // conv1 step
        int t2 = p - 2;   // conv2 step
        int t3 = p - 3;   // fc1 step
        int t4 = p - 4;   // fc2 step

        // ---- heavy units (conv1 + conv2), strided ----
        for (int u = blk; u < 864; u += NBLOCKS) {
            if (u < 576) {
                if (t1 < 0 || t1 >= TWIN) continue;
                const float* a0 = g_act0[t1 & 1];
                float* ap1 = g_actp1[t1 & 1];
                int bx = u & 15, b = u >> 4;
                int half = bx & 1, tc = (bx >> 1) & 3, tr = bx >> 3;
                conv_pool_unit<32, 16, 4, 64>(smem, a0, g_Wt1, b1,
                    g_c1_pre, g_p1_pre, ap1, half * 64, tr * 16, tc * 8, b);
            } else {
                if (t2 < 0 || t2 >= TWIN) continue;
                const float* ap1 = g_actp1[t2 & 1];
                float* ap2 = g_actp2[t2 & 1];
                int cu = u - 576;
                int bx = cu & 7, b = cu >> 3;
                int half = bx & 1, tc = (bx >> 1) & 1, tr = bx >> 2;
                conv_pool_unit<16, 8, 2, 128>(smem, ap1, g_Wt2, b2,
                    g_c2_pre, g_p2_pre, ap2, half * 64, tr * 8, tc * 8, b);
            }
        }

        // ---- conv0(p): blocks 0..431 one unit; 432..443 twelve each ----
        if (p < TWIN) {
            float* a0 = g_act0[p & 1];
            if (blk < 432) {
                conv0_unit(smem, W0, b0, a0, p, blk & 15, blk >> 4);
            } else {
                int u0 = 432 + (blk - 432) * 12;
                for (int u = u0; u < u0 + 12; u++)
                    conv0_unit(smem, W0, b0, a0, p, u & 15, u >> 4);
            }
        }

        // ---- fc1(t3): 192 units, one per block on 252..443 ----
        if (t3 >= 0 && t3 < TWIN && blk >= 252)
            fc1_unit(Wf1, bf1, g_actp2[t3 & 1], g_acth1[t3 & 1], blk - 252);

        // ---- fc2(t4): 50 units on blocks 432..443 ----
        if (t4 >= 0 && t4 < TWIN && blk >= 432) {
            const float* ah1 = g_acth1[t4 & 1];
            for (int u = blk - 432; u < 50; u += 12)
                fc2_unit(Wf2, bf2, ah1, u);
        }

        grid_barrier(epoch);
    }

    if (blk == 0)
        for (int i = tid; i < BATCH*11; i += 256)
            out[i] = g_acc[i] * (1.0f / (float)TWIN);
}

extern "C" void kernel_launch(void* const* d_in, const int* in_sizes, int n_in,
                              void* d_out, int out_size) {
    (void)in_sizes; (void)n_in; (void)out_size;
    const float* data = (const float*)d_in[0];
    const float* W0  = (const float*)d_in[2];
    const float* b0  = (const float*)d_in[3];
    const float* W1  = (const float*)d_in[4];
    const float* b1  = (const float*)d_in[5];
    const float* W2  = (const float*)d_in[6];
    const float* b2  = (const float*)d_in[7];
    const float* Wf1 = (const float*)d_in[8];
    const float* bf1 = (const float*)d_in[9];
    const float* Wf2 = (const float*)d_in[10];
    const float* bf2 = (const float*)d_in[11];

    zero_state_kernel<<<(BATCH*128*32*32 + 255)/256, 256>>>();
    prep_weights_kernel<<<(1152*128 + 255)/256, 256>>>(W1, W2);
    prep_bin_kernel<<<(TWIN*BATCH*2*32*32 + 255)/256, 256>>>(data);
    mega_kernel<<<NBLOCKS, 256>>>(W0, b0, b1, b2, Wf1, bf1, Wf2, bf2,
                                  (float*)d_out);
}